// round 15
// baseline (speedup 1.0000x reference)
#include <cuda_runtime.h>

#define NN 100000
#define NE 3200000
#define BKT 128          // fixed bucket capacity per node (Poisson(32) — safe)
#define NM1 100000       // layer-1 mask words (3.2M elements / 32)
#define NM2 200000       // layer-2 mask words (6.4M elements / 32)

// ---------------- scratch (device-only references) --------------------------
// g_cnt is zeroed by agg3's epilogue each call (device globals load as 0).
__device__ int g_cnt[NN];
__device__ int g_bkt[NN * BKT];          // stores src_byte_offset = src<<7
__device__ unsigned g_m1[NM1];           // dropout keep-masks, layer 1
__device__ unsigned g_m2[NM2];           // dropout keep-masks, layer 2
__device__ __align__(16) float g_p [NN * 32];   // projection buffer (reused)
__device__ __align__(16) float g_d1[NN * 32];   // layer-1 out (dropout, pre-scaled)
__device__ __align__(16) float g_d2[NN * 64];   // layer-2 out (post dropout)

template<int ID> __device__ __forceinline__ float* bufptr();
template<> __device__ __forceinline__ float* bufptr<0>() { return g_p;  }
template<> __device__ __forceinline__ float* bufptr<1>() { return g_d1; }
template<> __device__ __forceinline__ float* bufptr<2>() { return g_d2; }

// ---------------- JAX threefry2x32 ------------------------------------------
struct U2 { unsigned x, y; };

__host__ __device__ constexpr unsigned rotl32(unsigned v, int r) {
  return (v << r) | (v >> (32 - r));
}

__host__ __device__ constexpr U2 threefry2x32(unsigned k0, unsigned k1,
                                              unsigned c0, unsigned c1) {
  unsigned ks2 = k0 ^ k1 ^ 0x1BD11BDAu;
  unsigned x0 = c0 + k0;
  unsigned x1 = c1 + k1;
  x0 += x1; x1 = rotl32(x1, 13); x1 ^= x0;
  x0 += x1; x1 = rotl32(x1, 15); x1 ^= x0;
  x0 += x1; x1 = rotl32(x1, 26); x1 ^= x0;
  x0 += x1; x1 = rotl32(x1,  6); x1 ^= x0;
  x0 += k1;  x1 += ks2 + 1u;
  x0 += x1; x1 = rotl32(x1, 17); x1 ^= x0;
  x0 += x1; x1 = rotl32(x1, 29); x1 ^= x0;
  x0 += x1; x1 = rotl32(x1, 16); x1 ^= x0;
  x0 += x1; x1 = rotl32(x1, 24); x1 ^= x0;
  x0 += ks2; x1 += k0 + 2u;
  x0 += x1; x1 = rotl32(x1, 13); x1 ^= x0;
  x0 += x1; x1 = rotl32(x1, 15); x1 ^= x0;
  x0 += x1; x1 = rotl32(x1, 26); x1 ^= x0;
  x0 += x1; x1 = rotl32(x1,  6); x1 ^= x0;
  x0 += k0;  x1 += k1 + 3u;
  x0 += x1; x1 = rotl32(x1, 17); x1 ^= x0;
  x0 += x1; x1 = rotl32(x1, 29); x1 ^= x0;
  x0 += x1; x1 = rotl32(x1, 16); x1 ^= x0;
  x0 += x1; x1 = rotl32(x1, 24); x1 ^= x0;
  x0 += k1;  x1 += ks2 + 4u;
  x0 += x1; x1 = rotl32(x1, 13); x1 ^= x0;
  x0 += x1; x1 = rotl32(x1, 15); x1 ^= x0;
  x0 += x1; x1 = rotl32(x1, 26); x1 ^= x0;
  x0 += x1; x1 = rotl32(x1,  6); x1 ^= x0;
  x0 += ks2; x1 += k0 + 5u;
  return U2{x0, x1};
}

constexpr U2 DKEY1 = threefry2x32(0u, 42u, 0u, 0u);
constexpr U2 DKEY2 = threefry2x32(0u, 42u, 0u, 1u);

__device__ __forceinline__ float celu1(float v) {
  return v > 0.0f ? v : expm1f(v);
}

// keep-bit for element idx under key (ka,kb): top bit of x^y clear.
__device__ __forceinline__ unsigned keep_bit(unsigned ka, unsigned kb,
                                             unsigned idx) {
  U2 r = threefry2x32(ka, kb, 0u, idx);
  return (~(r.x ^ r.y)) >> 31;   // 1 = keep
}

// ---------------- graph preprocessing (edge_index is int32) -----------------
// One pass: counter doubles as bucket cursor; store BYTE OFFSET (src<<7).
// Atomics issued back-to-back (independent) so their round-trips overlap.
// Threads t < NM1+NM2 additionally compute one dropout mask word — pure ALU
// that fills this kernel's idle issue slots (proven free in R13).
__global__ void fill_kernel(const int* __restrict__ ei) {
  int t = blockIdx.x * blockDim.x + threadIdx.x;
  if (t >= NE / 4) return;
  int4 s4 = reinterpret_cast<const int4*>(ei)[t];
  int4 d4 = reinterpret_cast<const int4*>(ei + NE)[t];
  bool v0 = (unsigned)d4.x < (unsigned)NN;
  bool v1 = (unsigned)d4.y < (unsigned)NN;
  bool v2 = (unsigned)d4.z < (unsigned)NN;
  bool v3 = (unsigned)d4.w < (unsigned)NN;
  int p0 = 0, p1 = 0, p2 = 0, p3 = 0;
  if (v0) p0 = atomicAdd(&g_cnt[d4.x], 1);
  if (v1) p1 = atomicAdd(&g_cnt[d4.y], 1);
  if (v2) p2 = atomicAdd(&g_cnt[d4.z], 1);
  if (v3) p3 = atomicAdd(&g_cnt[d4.w], 1);

  // dropout mask generation (overlaps the atomic latency)
  if (t < NM1 + NM2) {
    unsigned ka, kb, base;
    if (t < NM1) { ka = DKEY1.x; kb = DKEY1.y; base = (unsigned)t * 32u; }
    else         { ka = DKEY2.x; kb = DKEY2.y; base = (unsigned)(t - NM1) * 32u; }
    unsigned m = 0;
    #pragma unroll 4
    for (int b = 0; b < 32; ++b)
      m |= keep_bit(ka, kb, base + (unsigned)b) << b;
    if (t < NM1) g_m1[t] = m; else g_m2[t - NM1] = m;
  }

  if (v0 && p0 < BKT) g_bkt[d4.x * BKT + p0] = s4.x << 7;
  if (v1 && p1 < BKT) g_bkt[d4.y * BKT + p1] = s4.y << 7;
  if (v2 && p2 < BKT) g_bkt[d4.z * BKT + p2] = s4.z << 7;
  if (v3 && p3 < BKT) g_bkt[d4.w * BKT + p3] = s4.w << 7;
}

// ---------------- dense projection: out = in @ W (+epilogue) ----------------
template<int FIN, int FOUT, int SCALE, int SRC, int DST>
__global__ void __launch_bounds__(256)
proj_kernel(const float* __restrict__ xin, const float* __restrict__ W) {
  __shared__ __align__(16) float sW[FIN * FOUT];
  for (int i = threadIdx.x; i < FIN * FOUT; i += 256) sW[i] = W[i];
  __syncthreads();

  const float* in = (SRC < 0) ? xin : bufptr<(SRC < 0) ? 0 : SRC>();
  float* out = bufptr<DST>();

  constexpr int TPN = FOUT / 4;
  int gid = blockIdx.x * blockDim.x + threadIdx.x;
  int n  = gid / TPN;
  int f4 = (gid % TPN) * 4;
  if (n >= NN) return;

  const float4* xrow = reinterpret_cast<const float4*>(in + (size_t)n * FIN);
  float a0 = 0.f, a1 = 0.f, a2 = 0.f, a3 = 0.f;
  #pragma unroll
  for (int k4 = 0; k4 < FIN / 4; ++k4) {
    float4 xv = xrow[k4];
    #pragma unroll
    for (int r = 0; r < 4; ++r) {
      float xs = (r == 0) ? xv.x : (r == 1) ? xv.y : (r == 2) ? xv.z : xv.w;
      float4 wv = *reinterpret_cast<const float4*>(&sW[(k4 * 4 + r) * FOUT + f4]);
      a0 += xs * wv.x; a1 += xs * wv.y; a2 += xs * wv.z; a3 += xs * wv.w;
    }
  }
  float sc = 1.0f;
  if (SCALE) sc = rsqrtf((float)(g_cnt[n] + 1));
  *reinterpret_cast<float4*>(out + n * FOUT + f4) =
      make_float4(a0 * sc, a1 * sc, a2 * sc, a3 * sc);
}

// ---------------- gather core: returns this lane's feature (f = lane) -------
__device__ __forceinline__ float gather_node(const float* p, int j, int deg,
                                             int lane) {
  int q = lane >> 3;
  int s = lane & 7;
  const char* pc = reinterpret_cast<const char*>(p) + (s << 4);
  int beg = j * BKT;

  unsigned long long a01 = 0ull, a23 = 0ull;
  if (q == 0) {
    ulonglong2 sv = __ldg(reinterpret_cast<const ulonglong2*>(pc + (size_t)j * 128));
    a01 = sv.x; a23 = sv.y;
  }

  for (int e = 0; e < deg; e += 32) {
    int n = deg - e;
    int offv = __ldg(&g_bkt[beg + e + lane]);
    #pragma unroll
    for (int k = 0; k < 8; ++k) {
      int t = k * 4 + q;
      int off = __shfl_sync(0xffffffffu, offv, t);
      if (t < n) {
        ulonglong2 v = __ldg(reinterpret_cast<const ulonglong2*>(pc + off));
        asm("add.rn.f32x2 %0, %0, %1;" : "+l"(a01) : "l"(v.x));
        asm("add.rn.f32x2 %0, %0, %1;" : "+l"(a23) : "l"(v.y));
      }
    }
  }

  float ax, ay, az, aw;
  asm("mov.b64 {%0, %1}, %2;" : "=f"(ax), "=f"(ay) : "l"(a01));
  asm("mov.b64 {%0, %1}, %2;" : "=f"(az), "=f"(aw) : "l"(a23));
  #pragma unroll
  for (int d = 8; d < 32; d <<= 1) {
    ax += __shfl_xor_sync(0xffffffffu, ax, d);
    ay += __shfl_xor_sync(0xffffffffu, ay, d);
    az += __shfl_xor_sync(0xffffffffu, az, d);
    aw += __shfl_xor_sync(0xffffffffu, aw, d);
  }
  int srcl = lane >> 2;
  float v0 = __shfl_sync(0xffffffffu, ax, srcl);
  float v1 = __shfl_sync(0xffffffffu, ay, srcl);
  float v2 = __shfl_sync(0xffffffffu, az, srcl);
  float v3 = __shfl_sync(0xffffffffu, aw, srcl);
  int r = lane & 3;
  return (r == 0) ? v0 : (r == 1) ? v1 : (r == 2) ? v2 : v3;
}

// ---------------- aggregation-only kernel (layers 1, 3) ----------------------
// POST: 1 = bias+celu+mask-dropout(g_m1), 2 = bias+celu.
// OUTSCALE: extra *dj on store. ZERO: reset g_cnt[j] (last user; next call's
// fill needs zeroed counters).
template<int POST, int OUTSCALE, int ZERO, int SRC, int DST>
__global__ void __launch_bounds__(256, 8)
agg_kernel(const float* __restrict__ bias, float* __restrict__ xout) {
  const float* p = bufptr<SRC>();
  float* out = (DST < 0) ? xout : bufptr<(DST < 0) ? 0 : DST>();

  int gid  = blockIdx.x * blockDim.x + threadIdx.x;
  int j    = gid >> 5;
  int lane = gid & 31;
  if (j >= NN) return;

  int deg = g_cnt[j];
  if (ZERO && lane == 0) g_cnt[j] = 0;
  float dj = rsqrtf((float)(deg + 1));
  float v = gather_node(p, j, deg, lane) * dj;

  v += bias[lane];
  v = celu1(v);
  if (POST == 1) {
    unsigned m = g_m1[j];
    v = ((m >> lane) & 1u) ? v * 2.0f : 0.0f;
  }
  if (OUTSCALE) v *= dj;
  out[j * 32 + lane] = v;
}

// ---------------- fused layer 2: agg(g_d1) -> @W2 -> bias/celu/mask-dropout --
__global__ void __launch_bounds__(256, 8)
agg2proj2_kernel(const float* __restrict__ W, const float* __restrict__ bias) {
  __shared__ __align__(16) float sW[32 * 64];
  for (int i = threadIdx.x; i < 32 * 64; i += 256) sW[i] = W[i];
  __syncthreads();

  const float* p = g_d1;
  float* out = g_d2;

  int gid  = blockIdx.x * blockDim.x + threadIdx.x;
  int j    = gid >> 5;
  int lane = gid & 31;
  if (j >= NN) return;

  int deg = g_cnt[j];
  float dj = rsqrtf((float)(deg + 1));
  float v = gather_node(p, j, deg, lane) * dj;   // feature f = lane of A@d1 row j

  float o0 = bias[lane];
  float o1 = bias[lane + 32];
  #pragma unroll
  for (int f = 0; f < 32; ++f) {
    float vf = __shfl_sync(0xffffffffu, v, f);
    o0 += vf * sW[f * 64 + lane];
    o1 += vf * sW[f * 64 + lane + 32];
  }
  o0 = celu1(o0);
  o1 = celu1(o1);
  unsigned m0 = g_m2[2 * j];
  unsigned m1 = g_m2[2 * j + 1];
  o0 = ((m0 >> lane) & 1u) ? o0 * 2.0f : 0.0f;
  o1 = ((m1 >> lane) & 1u) ? o1 * 2.0f : 0.0f;
  out[j * 64 + lane]      = o0;
  out[j * 64 + lane + 32] = o1;
}

// ---------------- launch -----------------------------------------------------
extern "C" void kernel_launch(void* const* d_in, const int* in_sizes, int n_in,
                              void* d_out, int out_size) {
  const float* x  = (const float*)d_in[0];
  const int*   ei = (const int*)d_in[1];      // int32 (JAX x64 disabled)
  const float* W1 = (const float*)d_in[2];
  const float* b1 = (const float*)d_in[3];
  const float* W2 = (const float*)d_in[4];
  const float* b2 = (const float*)d_in[5];
  const float* W3 = (const float*)d_in[6];
  const float* b3 = (const float*)d_in[7];
  float* out = (float*)d_out;

  const int E4 = (NE / 4 + 255) / 256;    // 3125
  const int WB = (NN * 32 + 255) / 256;   // 12500 (warp-per-node)

  // Adjacency build + masks (g_cnt pre-zeroed by previous call's agg3 /
  // zero-initialized device globals on the first call)
  fill_kernel<<<E4, 256>>>(ei);                                       // 1

  // Layer 1: g_p = dinv .* (x@W1) ; g_d1 = dinv .* mask(celu(dj*Σ + b1))
  proj_kernel<64, 32, 1, -1, 0><<<(NN * 8 + 255) / 256, 256>>>(x, W1);  // 2
  agg_kernel<1, 1, 0, 0, 1><<<WB, 256>>>(b1, nullptr);                // 3

  // Layer 2 (fused): g_d2 = mask(celu((dj*Σ g_d1) @ W2 + b2))
  agg2proj2_kernel<<<WB, 256>>>(W2, b2);                              // 4 (profiled)

  // Layer 3: g_p = dinv .* (g_d2@W3) ; out = celu(dj*Σ + b3) ; g_cnt := 0
  proj_kernel<64, 32, 1, 2, 0><<<(NN * 8 + 255) / 256, 256>>>(nullptr, W3);  // 5
  agg_kernel<2, 0, 1, 0, -1><<<WB, 256>>>(b3, out);                   // 6
}

// round 16
// speedup vs baseline: 1.2969x; 1.2969x over previous
#include <cuda_runtime.h>

#define NN 100000
#define NE 3200000
#define BKT 128          // fixed bucket capacity per node (Poisson(32) — safe)
#define NM1 100000       // layer-1 mask words (3.2M elements / 32)
#define NM2 200000       // layer-2 mask words (6.4M elements / 32)

// ---------------- scratch (device-only references) --------------------------
__device__ int g_cnt[NN];
__device__ int g_bkt[NN * BKT];          // stores src_byte_offset = src<<7
__device__ unsigned g_m1[NM1];           // dropout keep-masks, layer 1
__device__ unsigned g_m2[NM2];           // dropout keep-masks, layer 2
__device__ __align__(16) float g_p [NN * 32];   // shared 32-wide buffer
__device__ __align__(16) float g_d1[NN * 32];   // layer-1 out (pre-scaled)
__device__ __align__(16) float g_d2[NN * 64];   // layer-2 out (post dropout)

template<int ID> __device__ __forceinline__ float* bufptr();
template<> __device__ __forceinline__ float* bufptr<0>() { return g_p;  }
template<> __device__ __forceinline__ float* bufptr<1>() { return g_d1; }
template<> __device__ __forceinline__ float* bufptr<2>() { return g_d2; }

// ---------------- JAX threefry2x32 ------------------------------------------
struct U2 { unsigned x, y; };

__host__ __device__ constexpr unsigned rotl32(unsigned v, int r) {
  return (v << r) | (v >> (32 - r));
}

__host__ __device__ constexpr U2 threefry2x32(unsigned k0, unsigned k1,
                                              unsigned c0, unsigned c1) {
  unsigned ks2 = k0 ^ k1 ^ 0x1BD11BDAu;
  unsigned x0 = c0 + k0;
  unsigned x1 = c1 + k1;
  x0 += x1; x1 = rotl32(x1, 13); x1 ^= x0;
  x0 += x1; x1 = rotl32(x1, 15); x1 ^= x0;
  x0 += x1; x1 = rotl32(x1, 26); x1 ^= x0;
  x0 += x1; x1 = rotl32(x1,  6); x1 ^= x0;
  x0 += k1;  x1 += ks2 + 1u;
  x0 += x1; x1 = rotl32(x1, 17); x1 ^= x0;
  x0 += x1; x1 = rotl32(x1, 29); x1 ^= x0;
  x0 += x1; x1 = rotl32(x1, 16); x1 ^= x0;
  x0 += x1; x1 = rotl32(x1, 24); x1 ^= x0;
  x0 += ks2; x1 += k0 + 2u;
  x0 += x1; x1 = rotl32(x1, 13); x1 ^= x0;
  x0 += x1; x1 = rotl32(x1, 15); x1 ^= x0;
  x0 += x1; x1 = rotl32(x1, 26); x1 ^= x0;
  x0 += x1; x1 = rotl32(x1,  6); x1 ^= x0;
  x0 += k0;  x1 += k1 + 3u;
  x0 += x1; x1 = rotl32(x1, 17); x1 ^= x0;
  x0 += x1; x1 = rotl32(x1, 29); x1 ^= x0;
  x0 += x1; x1 = rotl32(x1, 16); x1 ^= x0;
  x0 += x1; x1 = rotl32(x1, 24); x1 ^= x0;
  x0 += k1;  x1 += ks2 + 4u;
  x0 += x1; x1 = rotl32(x1, 13); x1 ^= x0;
  x0 += x1; x1 = rotl32(x1, 15); x1 ^= x0;
  x0 += x1; x1 = rotl32(x1, 26); x1 ^= x0;
  x0 += x1; x1 = rotl32(x1,  6); x1 ^= x0;
  x0 += ks2; x1 += k0 + 5u;
  return U2{x0, x1};
}

constexpr U2 DKEY1 = threefry2x32(0u, 42u, 0u, 0u);
constexpr U2 DKEY2 = threefry2x32(0u, 42u, 0u, 1u);

__device__ __forceinline__ float celu1(float v) {
  return v > 0.0f ? v : expm1f(v);
}

// keep-bit for element idx under key (ka,kb): top bit of x^y clear.
__device__ __forceinline__ unsigned keep_bit(unsigned ka, unsigned kb,
                                             unsigned idx) {
  U2 r = threefry2x32(ka, kb, 0u, idx);
  return (~(r.x ^ r.y)) >> 31;   // 1 = keep
}

// ---------------- graph preprocessing (edge_index is int32) -----------------
__global__ void zero_cnt_kernel() {
  int i = blockIdx.x * blockDim.x + threadIdx.x;
  if (i < NN) g_cnt[i] = 0;
}

// One pass: counter doubles as bucket cursor; store BYTE OFFSET (src<<7).
// Atomics issued back-to-back; mask-gen ALU overlaps the atomic latency.
__global__ void fill_kernel(const int* __restrict__ ei) {
  int t = blockIdx.x * blockDim.x + threadIdx.x;
  if (t >= NE / 4) return;
  int4 s4 = reinterpret_cast<const int4*>(ei)[t];
  int4 d4 = reinterpret_cast<const int4*>(ei + NE)[t];
  bool v0 = (unsigned)d4.x < (unsigned)NN;
  bool v1 = (unsigned)d4.y < (unsigned)NN;
  bool v2 = (unsigned)d4.z < (unsigned)NN;
  bool v3 = (unsigned)d4.w < (unsigned)NN;
  int p0 = 0, p1 = 0, p2 = 0, p3 = 0;
  if (v0) p0 = atomicAdd(&g_cnt[d4.x], 1);
  if (v1) p1 = atomicAdd(&g_cnt[d4.y], 1);
  if (v2) p2 = atomicAdd(&g_cnt[d4.z], 1);
  if (v3) p3 = atomicAdd(&g_cnt[d4.w], 1);

  if (t < NM1 + NM2) {
    unsigned ka, kb, base;
    if (t < NM1) { ka = DKEY1.x; kb = DKEY1.y; base = (unsigned)t * 32u; }
    else         { ka = DKEY2.x; kb = DKEY2.y; base = (unsigned)(t - NM1) * 32u; }
    unsigned m = 0;
    #pragma unroll 4
    for (int b = 0; b < 32; ++b)
      m |= keep_bit(ka, kb, base + (unsigned)b) << b;
    if (t < NM1) g_m1[t] = m; else g_m2[t - NM1] = m;
  }

  if (v0 && p0 < BKT) g_bkt[d4.x * BKT + p0] = s4.x << 7;
  if (v1 && p1 < BKT) g_bkt[d4.y * BKT + p1] = s4.y << 7;
  if (v2 && p2 < BKT) g_bkt[d4.z * BKT + p2] = s4.z << 7;
  if (v3 && p3 < BKT) g_bkt[d4.w * BKT + p3] = s4.w << 7;
}

// ---------------- dense projection: out = in @ W (+epilogue) ----------------
// POST: 0 = none, 2 = bias+celu+mask-dropout(g_m2).
// SCALE: multiply output row by rsqrt(deg+1).
template<int FIN, int FOUT, int POST, int SCALE, int SRC, int DST>
__global__ void __launch_bounds__(256)
proj_kernel(const float* __restrict__ xin, const float* __restrict__ W,
            const float* __restrict__ bias) {
  __shared__ __align__(16) float sW[FIN * FOUT];
  for (int i = threadIdx.x; i < FIN * FOUT; i += 256) sW[i] = W[i];
  __syncthreads();

  const float* in = (SRC < 0) ? xin : bufptr<(SRC < 0) ? 0 : SRC>();
  float* out = bufptr<DST>();

  constexpr int TPN = FOUT / 4;
  int gid = blockIdx.x * blockDim.x + threadIdx.x;
  int n  = gid / TPN;
  int f4 = (gid % TPN) * 4;
  if (n >= NN) return;

  const float4* xrow = reinterpret_cast<const float4*>(in + (size_t)n * FIN);
  float a0 = 0.f, a1 = 0.f, a2 = 0.f, a3 = 0.f;
  #pragma unroll
  for (int k4 = 0; k4 < FIN / 4; ++k4) {
    float4 xv = xrow[k4];
    #pragma unroll
    for (int r = 0; r < 4; ++r) {
      float xs = (r == 0) ? xv.x : (r == 1) ? xv.y : (r == 2) ? xv.z : xv.w;
      float4 wv = *reinterpret_cast<const float4*>(&sW[(k4 * 4 + r) * FOUT + f4]);
      a0 += xs * wv.x; a1 += xs * wv.y; a2 += xs * wv.z; a3 += xs * wv.w;
    }
  }
  float vv[4] = {a0, a1, a2, a3};
  if (POST == 2) {
    unsigned ob = (unsigned)(n * FOUT + f4);
    unsigned m = g_m2[ob >> 5];
    #pragma unroll
    for (int r = 0; r < 4; ++r) {
      float v = vv[r] + bias[f4 + r];
      v = celu1(v);
      vv[r] = ((m >> ((ob + r) & 31u)) & 1u) ? v * 2.0f : 0.0f;
    }
  }
  if (SCALE) {
    float sc = rsqrtf((float)(g_cnt[n] + 1));
    #pragma unroll
    for (int r = 0; r < 4; ++r) vv[r] *= sc;
  }
  *reinterpret_cast<float4*>(out + n * FOUT + f4) =
      make_float4(vv[0], vv[1], vv[2], vv[3]);
}

// ---------------- gather core: returns this lane's feature (f = lane) -------
__device__ __forceinline__ float gather_node(const float* p, int j, int deg,
                                             int lane) {
  int q = lane >> 3;
  int s = lane & 7;
  const char* pc = reinterpret_cast<const char*>(p) + (s << 4);
  int beg = j * BKT;

  unsigned long long a01 = 0ull, a23 = 0ull;
  if (q == 0) {
    ulonglong2 sv = __ldg(reinterpret_cast<const ulonglong2*>(pc + (size_t)j * 128));
    a01 = sv.x; a23 = sv.y;
  }

  for (int e = 0; e < deg; e += 32) {
    int n = deg - e;
    int offv = __ldg(&g_bkt[beg + e + lane]);
    #pragma unroll
    for (int k = 0; k < 8; ++k) {
      int t = k * 4 + q;
      int off = __shfl_sync(0xffffffffu, offv, t);
      if (t < n) {
        ulonglong2 v = __ldg(reinterpret_cast<const ulonglong2*>(pc + off));
        asm("add.rn.f32x2 %0, %0, %1;" : "+l"(a01) : "l"(v.x));
        asm("add.rn.f32x2 %0, %0, %1;" : "+l"(a23) : "l"(v.y));
      }
    }
  }

  float ax, ay, az, aw;
  asm("mov.b64 {%0, %1}, %2;" : "=f"(ax), "=f"(ay) : "l"(a01));
  asm("mov.b64 {%0, %1}, %2;" : "=f"(az), "=f"(aw) : "l"(a23));
  #pragma unroll
  for (int d = 8; d < 32; d <<= 1) {
    ax += __shfl_xor_sync(0xffffffffu, ax, d);
    ay += __shfl_xor_sync(0xffffffffu, ay, d);
    az += __shfl_xor_sync(0xffffffffu, az, d);
    aw += __shfl_xor_sync(0xffffffffu, aw, d);
  }
  int srcl = lane >> 2;
  float v0 = __shfl_sync(0xffffffffu, ax, srcl);
  float v1 = __shfl_sync(0xffffffffu, ay, srcl);
  float v2 = __shfl_sync(0xffffffffu, az, srcl);
  float v3 = __shfl_sync(0xffffffffu, aw, srcl);
  int r = lane & 3;
  return (r == 0) ? v0 : (r == 1) ? v1 : (r == 2) ? v2 : v3;
}

// ---------------- aggregation kernel (layers 1, 2, 3) ------------------------
// POST: 0 = none, 1 = bias+celu+mask-dropout(g_m1), 2 = bias+celu.
// OUTSCALE: extra *dj on store.
template<int POST, int OUTSCALE, int SRC, int DST>
__global__ void __launch_bounds__(256, 8)
agg_kernel(const float* __restrict__ bias, float* __restrict__ xout) {
  const float* p = bufptr<SRC>();
  float* out = (DST < 0) ? xout : bufptr<(DST < 0) ? 0 : DST>();

  int gid  = blockIdx.x * blockDim.x + threadIdx.x;
  int j    = gid >> 5;
  int lane = gid & 31;
  if (j >= NN) return;

  int deg = g_cnt[j];
  float dj = rsqrtf((float)(deg + 1));
  float v = gather_node(p, j, deg, lane) * dj;

  if (POST >= 1) {
    v += bias[lane];
    v = celu1(v);
  }
  if (POST == 1) {
    unsigned m = g_m1[j];
    v = ((m >> lane) & 1u) ? v * 2.0f : 0.0f;
  }
  if (OUTSCALE) v *= dj;
  out[j * 32 + lane] = v;
}

// ---------------- launch -----------------------------------------------------
extern "C" void kernel_launch(void* const* d_in, const int* in_sizes, int n_in,
                              void* d_out, int out_size) {
  const float* x  = (const float*)d_in[0];
  const int*   ei = (const int*)d_in[1];      // int32 (JAX x64 disabled)
  const float* W1 = (const float*)d_in[2];
  const float* b1 = (const float*)d_in[3];
  const float* W2 = (const float*)d_in[4];
  const float* b2 = (const float*)d_in[5];
  const float* W3 = (const float*)d_in[6];
  const float* b3 = (const float*)d_in[7];
  float* out = (float*)d_out;

  const int E4 = (NE / 4 + 255) / 256;    // 3125
  const int WB = (NN * 32 + 255) / 256;   // 12500 (warp-per-node)

  // Adjacency build + dropout masks
  zero_cnt_kernel<<<(NN + 255) / 256, 256>>>();                       // 1
  fill_kernel<<<E4, 256>>>(ei);                                       // 2

  // Layer 1: g_p = dinv .* (x@W1) ; g_d1 = dinv .* mask1(celu(dj*Σ + b1))
  proj_kernel<64, 32, 0, 1, -1, 0><<<(NN * 8 + 255) / 256, 256>>>(x, W1, nullptr);  // 3
  agg_kernel<1, 1, 0, 1><<<WB, 256>>>(b1, nullptr);                   // 4 (profiled: agg1)

  // Layer 2 (split): g_p = dj*Σ(g_d1) ; g_d2 = mask2(celu(g_p@W2 + b2))
  agg_kernel<0, 0, 1, 0><<<WB, 256>>>(nullptr, nullptr);              // 5
  proj_kernel<32, 64, 2, 0, 0, 2><<<(NN * 16 + 255) / 256, 256>>>(nullptr, W2, b2);  // 6

  // Layer 3: g_p = dinv .* (g_d2@W3) ; out = celu(dj*Σ + b3)
  proj_kernel<64, 32, 0, 1, 2, 0><<<(NN * 8 + 255) / 256, 256>>>(nullptr, W3, nullptr);  // 7
  agg_kernel<2, 0, 0, -1><<<WB, 256>>>(b3, out);                      // 8
}

// round 17
// speedup vs baseline: 1.3070x; 1.0078x over previous
#include <cuda_runtime.h>

#define NN 100000
#define NE 3200000
#define BKT 128          // fixed bucket capacity per node (Poisson(32) — safe)
#define NM1 100000       // layer-1 mask words (3.2M elements / 32)
#define NM2 200000       // layer-2 mask words (6.4M elements / 32)

// ---------------- scratch (device-only references) --------------------------
__device__ int g_cnt[NN];
__device__ int g_bkt[NN * BKT];          // stores src_byte_offset = src<<7
__device__ unsigned g_m1[NM1];           // dropout keep-masks, layer 1
__device__ unsigned g_m2[NM2];           // dropout keep-masks, layer 2
__device__ __align__(16) float g_p [NN * 32];   // shared 32-wide buffer
__device__ __align__(16) float g_d1[NN * 32];   // layer-1 out (pre-scaled)

template<int ID> __device__ __forceinline__ float* bufptr();
template<> __device__ __forceinline__ float* bufptr<0>() { return g_p;  }
template<> __device__ __forceinline__ float* bufptr<1>() { return g_d1; }

// ---------------- JAX threefry2x32 ------------------------------------------
struct U2 { unsigned x, y; };

__host__ __device__ constexpr unsigned rotl32(unsigned v, int r) {
  return (v << r) | (v >> (32 - r));
}

__host__ __device__ constexpr U2 threefry2x32(unsigned k0, unsigned k1,
                                              unsigned c0, unsigned c1) {
  unsigned ks2 = k0 ^ k1 ^ 0x1BD11BDAu;
  unsigned x0 = c0 + k0;
  unsigned x1 = c1 + k1;
  x0 += x1; x1 = rotl32(x1, 13); x1 ^= x0;
  x0 += x1; x1 = rotl32(x1, 15); x1 ^= x0;
  x0 += x1; x1 = rotl32(x1, 26); x1 ^= x0;
  x0 += x1; x1 = rotl32(x1,  6); x1 ^= x0;
  x0 += k1;  x1 += ks2 + 1u;
  x0 += x1; x1 = rotl32(x1, 17); x1 ^= x0;
  x0 += x1; x1 = rotl32(x1, 29); x1 ^= x0;
  x0 += x1; x1 = rotl32(x1, 16); x1 ^= x0;
  x0 += x1; x1 = rotl32(x1, 24); x1 ^= x0;
  x0 += ks2; x1 += k0 + 2u;
  x0 += x1; x1 = rotl32(x1, 13); x1 ^= x0;
  x0 += x1; x1 = rotl32(x1, 15); x1 ^= x0;
  x0 += x1; x1 = rotl32(x1, 26); x1 ^= x0;
  x0 += x1; x1 = rotl32(x1,  6); x1 ^= x0;
  x0 += k0;  x1 += k1 + 3u;
  x0 += x1; x1 = rotl32(x1, 17); x1 ^= x0;
  x0 += x1; x1 = rotl32(x1, 29); x1 ^= x0;
  x0 += x1; x1 = rotl32(x1, 16); x1 ^= x0;
  x0 += x1; x1 = rotl32(x1, 24); x1 ^= x0;
  x0 += k1;  x1 += ks2 + 4u;
  x0 += x1; x1 = rotl32(x1, 13); x1 ^= x0;
  x0 += x1; x1 = rotl32(x1, 15); x1 ^= x0;
  x0 += x1; x1 = rotl32(x1, 26); x1 ^= x0;
  x0 += x1; x1 = rotl32(x1,  6); x1 ^= x0;
  x0 += ks2; x1 += k0 + 5u;
  return U2{x0, x1};
}

constexpr U2 DKEY1 = threefry2x32(0u, 42u, 0u, 0u);
constexpr U2 DKEY2 = threefry2x32(0u, 42u, 0u, 1u);

__device__ __forceinline__ float celu1(float v) {
  return v > 0.0f ? v : expm1f(v);
}

// keep-bit for element idx under key (ka,kb): top bit of x^y clear.
__device__ __forceinline__ unsigned keep_bit(unsigned ka, unsigned kb,
                                             unsigned idx) {
  U2 r = threefry2x32(ka, kb, 0u, idx);
  return (~(r.x ^ r.y)) >> 31;   // 1 = keep
}

// ---------------- graph preprocessing (edge_index is int32) -----------------
__global__ void zero_cnt_kernel() {
  int i = blockIdx.x * blockDim.x + threadIdx.x;
  if (i < NN) g_cnt[i] = 0;
}

// One pass: counter doubles as bucket cursor; store BYTE OFFSET (src<<7).
// Atomics issued back-to-back; mask-gen ALU overlaps the atomic latency.
__global__ void fill_kernel(const int* __restrict__ ei) {
  int t = blockIdx.x * blockDim.x + threadIdx.x;
  if (t >= NE / 4) return;
  int4 s4 = reinterpret_cast<const int4*>(ei)[t];
  int4 d4 = reinterpret_cast<const int4*>(ei + NE)[t];
  bool v0 = (unsigned)d4.x < (unsigned)NN;
  bool v1 = (unsigned)d4.y < (unsigned)NN;
  bool v2 = (unsigned)d4.z < (unsigned)NN;
  bool v3 = (unsigned)d4.w < (unsigned)NN;
  int p0 = 0, p1 = 0, p2 = 0, p3 = 0;
  if (v0) p0 = atomicAdd(&g_cnt[d4.x], 1);
  if (v1) p1 = atomicAdd(&g_cnt[d4.y], 1);
  if (v2) p2 = atomicAdd(&g_cnt[d4.z], 1);
  if (v3) p3 = atomicAdd(&g_cnt[d4.w], 1);

  if (t < NM1 + NM2) {
    unsigned ka, kb, base;
    if (t < NM1) { ka = DKEY1.x; kb = DKEY1.y; base = (unsigned)t * 32u; }
    else         { ka = DKEY2.x; kb = DKEY2.y; base = (unsigned)(t - NM1) * 32u; }
    unsigned m = 0;
    #pragma unroll 4
    for (int b = 0; b < 32; ++b)
      m |= keep_bit(ka, kb, base + (unsigned)b) << b;
    if (t < NM1) g_m1[t] = m; else g_m2[t - NM1] = m;
  }

  if (v0 && p0 < BKT) g_bkt[d4.x * BKT + p0] = s4.x << 7;
  if (v1 && p1 < BKT) g_bkt[d4.y * BKT + p1] = s4.y << 7;
  if (v2 && p2 < BKT) g_bkt[d4.z * BKT + p2] = s4.z << 7;
  if (v3 && p3 < BKT) g_bkt[d4.w * BKT + p3] = s4.w << 7;
}

// ---------------- dense projection: out = in @ W (layer 1 front) -------------
// SCALE: multiply output row by rsqrt(deg+1).
template<int FIN, int FOUT, int SCALE, int SRC, int DST>
__global__ void __launch_bounds__(256)
proj_kernel(const float* __restrict__ xin, const float* __restrict__ W) {
  __shared__ __align__(16) float sW[FIN * FOUT];
  for (int i = threadIdx.x; i < FIN * FOUT; i += 256) sW[i] = W[i];
  __syncthreads();

  const float* in = (SRC < 0) ? xin : bufptr<(SRC < 0) ? 0 : SRC>();
  float* out = bufptr<DST>();

  constexpr int TPN = FOUT / 4;
  int gid = blockIdx.x * blockDim.x + threadIdx.x;
  int n  = gid / TPN;
  int f4 = (gid % TPN) * 4;
  if (n >= NN) return;

  const float4* xrow = reinterpret_cast<const float4*>(in + (size_t)n * FIN);
  float a0 = 0.f, a1 = 0.f, a2 = 0.f, a3 = 0.f;
  #pragma unroll
  for (int k4 = 0; k4 < FIN / 4; ++k4) {
    float4 xv = xrow[k4];
    #pragma unroll
    for (int r = 0; r < 4; ++r) {
      float xs = (r == 0) ? xv.x : (r == 1) ? xv.y : (r == 2) ? xv.z : xv.w;
      float4 wv = *reinterpret_cast<const float4*>(&sW[(k4 * 4 + r) * FOUT + f4]);
      a0 += xs * wv.x; a1 += xs * wv.y; a2 += xs * wv.z; a3 += xs * wv.w;
    }
  }
  float sc = 1.0f;
  if (SCALE) sc = rsqrtf((float)(g_cnt[n] + 1));
  *reinterpret_cast<float4*>(out + n * FOUT + f4) =
      make_float4(a0 * sc, a1 * sc, a2 * sc, a3 * sc);
}

// ---------------- fused proj2+proj3 through SMEM ------------------------------
// Block = 16 nodes. Phase 1 (16 thr/node): h64 = mask2(celu(g_p@W2 + b2)) -> smem.
// Phase 2 (8 thr/node): g_p = rsqrt(deg+1) * (h64 @ W3).  g_d2 never exists.
// FP orders identical to the split proj kernels (k ascending).
__global__ void __launch_bounds__(256)
proj23_kernel(const float* __restrict__ W2, const float* __restrict__ b2,
              const float* __restrict__ W3) {
  __shared__ __align__(16) float sW2[32 * 64];
  __shared__ __align__(16) float sW3[64 * 32];
  __shared__ __align__(16) float sH[16 * 64];
  for (int i = threadIdx.x; i < 32 * 64; i += 256) sW2[i] = W2[i];
  for (int i = threadIdx.x; i < 64 * 32; i += 256) sW3[i] = W3[i];
  __syncthreads();

  int tid = threadIdx.x;

  // ---- phase 1: 16 threads per node, 4 outputs each (64-wide h) ----
  {
    int bn = tid >> 4;                 // 0..15 node-in-block
    int f4 = (tid & 15) * 4;           // 0..60
    int n = blockIdx.x * 16 + bn;      // NN = 6250*16 exactly
    const float4* xrow = reinterpret_cast<const float4*>(g_p + (size_t)n * 32);
    float a0 = 0.f, a1 = 0.f, a2 = 0.f, a3 = 0.f;
    #pragma unroll
    for (int k4 = 0; k4 < 8; ++k4) {
      float4 xv = xrow[k4];
      #pragma unroll
      for (int r = 0; r < 4; ++r) {
        float xs = (r == 0) ? xv.x : (r == 1) ? xv.y : (r == 2) ? xv.z : xv.w;
        float4 wv = *reinterpret_cast<const float4*>(&sW2[(k4 * 4 + r) * 64 + f4]);
        a0 += xs * wv.x; a1 += xs * wv.y; a2 += xs * wv.z; a3 += xs * wv.w;
      }
    }
    unsigned ob = (unsigned)(n * 64 + f4);
    unsigned m = g_m2[ob >> 5];
    float vv[4] = {a0, a1, a2, a3};
    #pragma unroll
    for (int r = 0; r < 4; ++r) {
      float v = vv[r] + b2[f4 + r];
      v = celu1(v);
      vv[r] = ((m >> ((ob + r) & 31u)) & 1u) ? v * 2.0f : 0.0f;
    }
    *reinterpret_cast<float4*>(&sH[bn * 64 + f4]) =
        make_float4(vv[0], vv[1], vv[2], vv[3]);
  }
  __syncthreads();

  // ---- phase 2: 8 threads per node, 4 outputs each (32-wide) ----
  if (tid < 128) {
    int bn = tid >> 3;                 // 0..15
    int f4 = (tid & 7) * 4;            // 0..28
    int n = blockIdx.x * 16 + bn;
    const float4* hrow = reinterpret_cast<const float4*>(&sH[bn * 64]);
    float a0 = 0.f, a1 = 0.f, a2 = 0.f, a3 = 0.f;
    #pragma unroll
    for (int k4 = 0; k4 < 16; ++k4) {
      float4 xv = hrow[k4];
      #pragma unroll
      for (int r = 0; r < 4; ++r) {
        float xs = (r == 0) ? xv.x : (r == 1) ? xv.y : (r == 2) ? xv.z : xv.w;
        float4 wv = *reinterpret_cast<const float4*>(&sW3[(k4 * 4 + r) * 32 + f4]);
        a0 += xs * wv.x; a1 += xs * wv.y; a2 += xs * wv.z; a3 += xs * wv.w;
      }
    }
    float sc = rsqrtf((float)(g_cnt[n] + 1));
    *reinterpret_cast<float4*>(g_p + (size_t)n * 32 + f4) =
        make_float4(a0 * sc, a1 * sc, a2 * sc, a3 * sc);
  }
}

// ---------------- gather core: returns this lane's feature (f = lane) -------
__device__ __forceinline__ float gather_node(const float* p, int j, int deg,
                                             int lane) {
  int q = lane >> 3;
  int s = lane & 7;
  const char* pc = reinterpret_cast<const char*>(p) + (s << 4);
  int beg = j * BKT;

  unsigned long long a01 = 0ull, a23 = 0ull;
  if (q == 0) {
    ulonglong2 sv = __ldg(reinterpret_cast<const ulonglong2*>(pc + (size_t)j * 128));
    a01 = sv.x; a23 = sv.y;
  }

  for (int e = 0; e < deg; e += 32) {
    int n = deg - e;
    int offv = __ldg(&g_bkt[beg + e + lane]);
    #pragma unroll
    for (int k = 0; k < 8; ++k) {
      int t = k * 4 + q;
      int off = __shfl_sync(0xffffffffu, offv, t);
      if (t < n) {
        ulonglong2 v = __ldg(reinterpret_cast<const ulonglong2*>(pc + off));
        asm("add.rn.f32x2 %0, %0, %1;" : "+l"(a01) : "l"(v.x));
        asm("add.rn.f32x2 %0, %0, %1;" : "+l"(a23) : "l"(v.y));
      }
    }
  }

  float ax, ay, az, aw;
  asm("mov.b64 {%0, %1}, %2;" : "=f"(ax), "=f"(ay) : "l"(a01));
  asm("mov.b64 {%0, %1}, %2;" : "=f"(az), "=f"(aw) : "l"(a23));
  #pragma unroll
  for (int d = 8; d < 32; d <<= 1) {
    ax += __shfl_xor_sync(0xffffffffu, ax, d);
    ay += __shfl_xor_sync(0xffffffffu, ay, d);
    az += __shfl_xor_sync(0xffffffffu, az, d);
    aw += __shfl_xor_sync(0xffffffffu, aw, d);
  }
  int srcl = lane >> 2;
  float v0 = __shfl_sync(0xffffffffu, ax, srcl);
  float v1 = __shfl_sync(0xffffffffu, ay, srcl);
  float v2 = __shfl_sync(0xffffffffu, az, srcl);
  float v3 = __shfl_sync(0xffffffffu, aw, srcl);
  int r = lane & 3;
  return (r == 0) ? v0 : (r == 1) ? v1 : (r == 2) ? v2 : v3;
}

// ---------------- aggregation kernel (layers 1, 2, 3) ------------------------
// POST: 0 = none, 1 = bias+celu+mask-dropout(g_m1), 2 = bias+celu.
// OUTSCALE: extra *dj on store.
template<int POST, int OUTSCALE, int SRC, int DST>
__global__ void __launch_bounds__(256, 8)
agg_kernel(const float* __restrict__ bias, float* __restrict__ xout) {
  const float* p = bufptr<SRC>();
  float* out = (DST < 0) ? xout : bufptr<(DST < 0) ? 0 : DST>();

  int gid  = blockIdx.x * blockDim.x + threadIdx.x;
  int j    = gid >> 5;
  int lane = gid & 31;
  if (j >= NN) return;

  int deg = g_cnt[j];
  float dj = rsqrtf((float)(deg + 1));
  float v = gather_node(p, j, deg, lane) * dj;

  if (POST >= 1) {
    v += bias[lane];
    v = celu1(v);
  }
  if (POST == 1) {
    unsigned m = g_m1[j];
    v = ((m >> lane) & 1u) ? v * 2.0f : 0.0f;
  }
  if (OUTSCALE) v *= dj;
  out[j * 32 + lane] = v;
}

// ---------------- launch -----------------------------------------------------
extern "C" void kernel_launch(void* const* d_in, const int* in_sizes, int n_in,
                              void* d_out, int out_size) {
  const float* x  = (const float*)d_in[0];
  const int*   ei = (const int*)d_in[1];      // int32 (JAX x64 disabled)
  const float* W1 = (const float*)d_in[2];
  const float* b1 = (const float*)d_in[3];
  const float* W2 = (const float*)d_in[4];
  const float* b2 = (const float*)d_in[5];
  const float* W3 = (const float*)d_in[6];
  const float* b3 = (const float*)d_in[7];
  float* out = (float*)d_out;

  const int E4 = (NE / 4 + 255) / 256;    // 3125
  const int WB = (NN * 32 + 255) / 256;   // 12500 (warp-per-node)

  // Adjacency build + dropout masks
  zero_cnt_kernel<<<(NN + 255) / 256, 256>>>();                       // 1
  fill_kernel<<<E4, 256>>>(ei);                                       // 2

  // Layer 1: g_p = dinv .* (x@W1) ; g_d1 = dinv .* mask1(celu(dj*Σ + b1))
  proj_kernel<64, 32, 1, -1, 0><<<(NN * 8 + 255) / 256, 256>>>(x, W1);  // 3
  agg_kernel<1, 1, 0, 1><<<WB, 256>>>(b1, nullptr);                   // 4 (profiled: agg1)

  // Layer 2 gather: g_p = dj*Σ(g_d1)
  agg_kernel<0, 0, 1, 0><<<WB, 256>>>(nullptr, nullptr);              // 5

  // Fused layers 2/3 dense: g_p = dinv .* (mask2(celu(g_p@W2+b2)) @ W3)
  proj23_kernel<<<NN / 16, 256>>>(W2, b2, W3);                        // 6

  // Layer 3 gather: out = celu(dj*Σ(g_p) + b3)
  agg_kernel<2, 0, 0, -1><<<WB, 256>>>(b3, out);                      // 7
}